// round 4
// baseline (speedup 1.0000x reference)
#include <cuda_runtime.h>
#include <cuda_bf16.h>
#include <cstdint>
#include <math.h>

// Problem constants
#define BB 2
#define TT 2048
#define CC 1024
#define HH 16
#define DD 64
#define MROWS (BB*TT)          // 4096
#define KDIM  CC               // 1024
#define NDIM  CC               // 1024 per weight
#define EPS_DEN 1e-6f
#define LN_EPS  1e-5f

// ---------------- scratch (device globals; no allocation allowed) ----------------
__device__ float g_q[MROWS*CC];
__device__ float g_k[MROWS*CC];
__device__ float g_v[MROWS*CC];
__device__ float g_attn[MROWS*CC];
__device__ float g_y[MROWS*CC];
__device__ float g_f[BB*HH*TT];

// ============================================================================
// GEMM: out[m][n] = sum_k A[m][k] * W[n][k]  (A: MROWS x K, W: N x K, row-major)
// 128x128 block tile, BK=16, 256 threads, 8x8 per thread, double-buffered smem.
// mode 0: A = x (param), three weights -> g_q/g_k/g_v   (grid.x = 24)
// mode 1: A = g_attn,    W0 = Wo -> g_y, + bias + residual (grid.x = 8)
// ============================================================================
__global__ __launch_bounds__(256) void sgemm_kernel(
    int mode,
    const float* __restrict__ Ain,
    const float* __restrict__ W0, const float* __restrict__ W1, const float* __restrict__ W2,
    const float* __restrict__ bias, const float* __restrict__ residual)
{
    const int bn   = blockIdx.x;
    const int wsel = bn >> 3;               // 8 n-blocks per weight
    const int n0   = (bn & 7) * 128;
    const int m0   = blockIdx.y * 128;

    const float* A = (mode == 0) ? Ain : g_attn;
    const float* W = (wsel == 0) ? W0 : (wsel == 1 ? W1 : W2);
    float* O;
    if (mode == 0) O = (wsel == 0) ? g_q : (wsel == 1 ? g_k : g_v);
    else           O = g_y;

    __shared__ float As[2][16][132];
    __shared__ float Bs[2][16][132];

    const int tid  = threadIdx.x;
    const int lrow = tid >> 2;              // 0..63
    const int lk4  = (tid & 3) << 2;        // 0,4,8,12

    const float* Aptr0 = A + (size_t)(m0 + lrow) * KDIM + lk4;
    const float* Aptr1 = Aptr0 + (size_t)64 * KDIM;
    const float* Wptr0 = W + (size_t)(n0 + lrow) * KDIM + lk4;
    const float* Wptr1 = Wptr0 + (size_t)64 * KDIM;

    // load tile 0
    {
        float4 a0 = *(const float4*)Aptr0;
        float4 a1 = *(const float4*)Aptr1;
        float4 b0 = *(const float4*)Wptr0;
        float4 b1 = *(const float4*)Wptr1;
        As[0][lk4+0][lrow] = a0.x; As[0][lk4+1][lrow] = a0.y;
        As[0][lk4+2][lrow] = a0.z; As[0][lk4+3][lrow] = a0.w;
        As[0][lk4+0][lrow+64] = a1.x; As[0][lk4+1][lrow+64] = a1.y;
        As[0][lk4+2][lrow+64] = a1.z; As[0][lk4+3][lrow+64] = a1.w;
        Bs[0][lk4+0][lrow] = b0.x; Bs[0][lk4+1][lrow] = b0.y;
        Bs[0][lk4+2][lrow] = b0.z; Bs[0][lk4+3][lrow] = b0.w;
        Bs[0][lk4+0][lrow+64] = b1.x; Bs[0][lk4+1][lrow+64] = b1.y;
        Bs[0][lk4+2][lrow+64] = b1.z; Bs[0][lk4+3][lrow+64] = b1.w;
    }
    __syncthreads();

    const int tx = (tid & 15) << 3;   // n offset in tile
    const int ty = (tid >> 4) << 3;   // m offset in tile

    float acc[8][8];
    #pragma unroll
    for (int i = 0; i < 8; i++)
        #pragma unroll
        for (int j = 0; j < 8; j++) acc[i][j] = 0.f;

    const int NT = KDIM / 16;
    for (int it = 0; it < NT; it++) {
        const int cur = it & 1;
        const bool more = (it + 1 < NT);
        float4 na0, na1, nb0, nb1;
        if (more) {
            const int off = (it + 1) * 16;
            na0 = *(const float4*)(Aptr0 + off);
            na1 = *(const float4*)(Aptr1 + off);
            nb0 = *(const float4*)(Wptr0 + off);
            nb1 = *(const float4*)(Wptr1 + off);
        }
        #pragma unroll
        for (int kk = 0; kk < 16; kk++) {
            float ar[8], br[8];
            *(float4*)&ar[0] = *(const float4*)&As[cur][kk][ty];
            *(float4*)&ar[4] = *(const float4*)&As[cur][kk][ty+4];
            *(float4*)&br[0] = *(const float4*)&Bs[cur][kk][tx];
            *(float4*)&br[4] = *(const float4*)&Bs[cur][kk][tx+4];
            #pragma unroll
            for (int i = 0; i < 8; i++)
                #pragma unroll
                for (int j = 0; j < 8; j++)
                    acc[i][j] = fmaf(ar[i], br[j], acc[i][j]);
        }
        if (more) {
            __syncthreads();
            const int nb = cur ^ 1;
            As[nb][lk4+0][lrow] = na0.x; As[nb][lk4+1][lrow] = na0.y;
            As[nb][lk4+2][lrow] = na0.z; As[nb][lk4+3][lrow] = na0.w;
            As[nb][lk4+0][lrow+64] = na1.x; As[nb][lk4+1][lrow+64] = na1.y;
            As[nb][lk4+2][lrow+64] = na1.z; As[nb][lk4+3][lrow+64] = na1.w;
            Bs[nb][lk4+0][lrow] = nb0.x; Bs[nb][lk4+1][lrow] = nb0.y;
            Bs[nb][lk4+2][lrow] = nb0.z; Bs[nb][lk4+3][lrow] = nb0.w;
            Bs[nb][lk4+0][lrow+64] = nb1.x; Bs[nb][lk4+1][lrow+64] = nb1.y;
            Bs[nb][lk4+2][lrow+64] = nb1.z; Bs[nb][lk4+3][lrow+64] = nb1.w;
            __syncthreads();
        }
    }

    // epilogue
    #pragma unroll
    for (int i = 0; i < 8; i++) {
        const int gm = m0 + ty + i;
        #pragma unroll
        for (int jj = 0; jj < 8; jj += 4) {
            const int gn = n0 + tx + jj;
            float4 r = make_float4(acc[i][jj], acc[i][jj+1], acc[i][jj+2], acc[i][jj+3]);
            if (bias) {
                float4 bb = *(const float4*)(bias + gn);
                r.x += bb.x; r.y += bb.y; r.z += bb.z; r.w += bb.w;
            }
            if (residual) {
                float4 rr = *(const float4*)(residual + (size_t)gm * NDIM + gn);
                r.x += rr.x; r.y += rr.y; r.z += rr.z; r.w += rr.w;
            }
            *(float4*)(O + (size_t)gm * NDIM + gn) = r;
        }
    }
}

// ============================================================================
// gate: f[b][h][t] = mask-adjusted clip(sigmoid(x_row . Wg[h] + bg[h]))
// 128 threads: 8 rows x 16 heads per block. grid = 512.
// ============================================================================
__global__ __launch_bounds__(128) void f_kernel(
    const float* __restrict__ x, const float* __restrict__ Wg,
    const float* __restrict__ bg, const int* __restrict__ mask)
{
    const int tid = threadIdx.x;
    const int r = tid >> 4, h = tid & 15;
    const int row = blockIdx.x * 8 + r;
    const float4* xr = (const float4*)(x + (size_t)row * CC);
    const float4* wr = (const float4*)(Wg + (size_t)h * CC);
    float s = 0.f;
    #pragma unroll 8
    for (int kk = 0; kk < CC/4; kk++) {
        float4 a = xr[kk], w = wr[kk];
        s = fmaf(a.x, w.x, s); s = fmaf(a.y, w.y, s);
        s = fmaf(a.z, w.z, s); s = fmaf(a.w, w.w, s);
    }
    s += bg[h];
    float fv = 1.0f / (1.0f + expf(-s));
    fv = fminf(fmaxf(fv, 0.01f), 0.999f);
    const float mk = (float)mask[row];
    fv = fv * mk + (1.0f - mk);
    const int b = row >> 11, t = row & (TT - 1);
    g_f[((size_t)(b * HH + h)) * TT + t] = fv;
}

// ============================================================================
// RoPE + phi (elu+1) + mask, in place on g_q / g_k. One warp per (b,t,h).
// grid = (8192, 2), block 256.
// inv_freq computed via double pow -> correctly-rounded f32 (matches jax's
// f32 power to <=1 ulp), then phase & sincos in f32 mirroring the reference.
// ============================================================================
__global__ __launch_bounds__(256) void rope_phi_kernel(const int* __restrict__ mask)
{
    const int wid  = blockIdx.x * 8 + (threadIdx.x >> 5);   // 0..65535
    const int lane = threadIdx.x & 31;
    const int h    = wid & 15;
    const int row  = wid >> 4;            // b*T + t
    const int t    = row & (TT - 1);

    float* ptr = (blockIdx.y ? g_k : g_q) + (size_t)row * CC + h * DD;
    const float x1 = ptr[lane];
    const float x2 = ptr[lane + 32];

    // inv_freq = 1 / 10000^(lane/32): correctly-rounded via double
    const float inv = (float)(1.0 / pow(10000.0, (double)lane * (1.0 / 32.0)));
    const float fr  = (float)t * inv;     // same f32 multiply as reference
    float c, s;
    sincosf(fr, &s, &c);

    float y1 = x1 * c - x2 * s;
    float y2 = x2 * c + x1 * s;
    y1 = (y1 > 0.f) ? (y1 + 1.f) : expf(y1);
    y2 = (y2 > 0.f) ? (y2 + 1.f) : expf(y2);
    const float mk = (float)mask[row];
    ptr[lane]      = y1 * mk;
    ptr[lane + 32] = y2 * mk;
}

// ============================================================================
// Gated linear-attention scan, split 4-way over the value dim e.
// Grid = 128: block bx -> (bh = bx>>2, e0 = (bx&3)*16). The S-recurrence is
// columnwise independent in e; m/den are recomputed redundantly per slice.
// 256 threads: g = tid&15 owns d in [g*4, g*4+4); e = e0 + (tid>>4).
// d-reduction: 4x shfl.xor (offsets 1,2,4,8) — intra-warp.
// q/k/v/f staged to smem in 16-step chunks.
// ============================================================================
#define SCHUNK 16
__global__ __launch_bounds__(256) void scan_kernel()
{
    const int bx = blockIdx.x;            // 0..127
    const int bh = bx >> 2;               // b*16 + h
    const int e0 = (bx & 3) * 16;
    const int b = bh >> 4, h = bh & 15;
    const int tid = threadIdx.x;
    const int g = tid & 15;               // d-group: d in [g*4, g*4+4)
    const int e = e0 + (tid >> 4);        // value index owned by this thread

    __shared__ float qs[SCHUNK][64], ks[SCHUNK][64], vs[SCHUNK][64], fs[SCHUNK];

    float S[4], m[4];
    #pragma unroll
    for (int j = 0; j < 4; j++) { S[j] = 0.f; m[j] = 0.f; }

    const size_t base = (size_t)(b * TT) * CC + h * DD;
    const float* fptr = g_f + (size_t)bh * TT;

    const int r  = tid >> 4;        // staging: row in chunk
    const int cv = (tid & 15) * 4;  // staging: float4 offset

    for (int c = 0; c < TT / SCHUNK; c++) {
        __syncthreads();
        {
            const size_t roff = base + (size_t)(c * SCHUNK + r) * CC + cv;
            *(float4*)&qs[r][cv] = *(const float4*)(g_q + roff);
            *(float4*)&ks[r][cv] = *(const float4*)(g_k + roff);
            *(float4*)&vs[r][cv] = *(const float4*)(g_v + roff);
            if (tid < SCHUNK) fs[tid] = fptr[c * SCHUNK + tid];
        }
        __syncthreads();

        #pragma unroll 4
        for (int i = 0; i < SCHUNK; i++) {
            const float ft = fs[i];
            const float ve = vs[i][e];
            float kreg[4], qreg[4];
            *(float4*)&kreg[0] = *(const float4*)&ks[i][g*4];
            *(float4*)&qreg[0] = *(const float4*)&qs[i][g*4];

            float num = 0.f, den = 0.f;
            #pragma unroll
            for (int j = 0; j < 4; j++) {
                const float kv = kreg[j] * ve;
                S[j] = fmaf(ft, S[j], kv);
                num  = fmaf(qreg[j], S[j], num);
                m[j] = fmaf(ft, m[j], kreg[j]);
                den  = fmaf(qreg[j], m[j], den);
            }
            num += __shfl_xor_sync(0xFFFFFFFFu, num, 1);
            num += __shfl_xor_sync(0xFFFFFFFFu, num, 2);
            num += __shfl_xor_sync(0xFFFFFFFFu, num, 4);
            num += __shfl_xor_sync(0xFFFFFFFFu, num, 8);
            den += __shfl_xor_sync(0xFFFFFFFFu, den, 1);
            den += __shfl_xor_sync(0xFFFFFFFFu, den, 2);
            den += __shfl_xor_sync(0xFFFFFFFFu, den, 4);
            den += __shfl_xor_sync(0xFFFFFFFFu, den, 8);
            if (g == 0) {
                g_attn[base + (size_t)(c * SCHUNK + i) * CC + e] = num / fmaxf(den, EPS_DEN);
            }
        }
    }
}

// ============================================================================
// LayerNorm over rows of g_y -> out. One block per row (4096), 256 threads.
// ============================================================================
__global__ __launch_bounds__(256) void ln_kernel(
    const float* __restrict__ lnw, const float* __restrict__ lnb,
    float* __restrict__ out)
{
    const int row = blockIdx.x;
    const int tid = threadIdx.x;
    const float4 v = ((const float4*)(g_y + (size_t)row * CC))[tid];
    float s  = v.x + v.y + v.z + v.w;
    float ss = v.x*v.x + v.y*v.y + v.z*v.z + v.w*v.w;

    #pragma unroll
    for (int o = 16; o > 0; o >>= 1) {
        s  += __shfl_xor_sync(0xFFFFFFFFu, s,  o);
        ss += __shfl_xor_sync(0xFFFFFFFFu, ss, o);
    }
    __shared__ float red[16];
    const int wid = tid >> 5, lane = tid & 31;
    if (lane == 0) { red[wid] = s; red[wid + 8] = ss; }
    __syncthreads();
    float ts = 0.f, tss = 0.f;
    #pragma unroll
    for (int i = 0; i < 8; i++) { ts += red[i]; tss += red[i + 8]; }

    const float mu   = ts * (1.0f / CC);
    const float var  = tss * (1.0f / CC) - mu * mu;
    const float rstd = rsqrtf(var + LN_EPS);

    const float4 wv = ((const float4*)lnw)[tid];
    const float4 bv = ((const float4*)lnb)[tid];
    float4 o;
    o.x = (v.x - mu) * rstd * wv.x + bv.x;
    o.y = (v.y - mu) * rstd * wv.y + bv.y;
    o.z = (v.z - mu) * rstd * wv.z + bv.z;
    o.w = (v.w - mu) * rstd * wv.w + bv.w;
    ((float4*)(out + (size_t)row * CC))[tid] = o;
}

// ============================================================================
extern "C" void kernel_launch(void* const* d_in, const int* in_sizes, int n_in,
                              void* d_out, int out_size)
{
    const float* x    = (const float*)d_in[0];
    const int*   mask = (const int*)  d_in[1];
    const float* Wq   = (const float*)d_in[2];
    const float* Wk   = (const float*)d_in[3];
    const float* Wv   = (const float*)d_in[4];
    const float* Wg   = (const float*)d_in[5];
    const float* bg   = (const float*)d_in[6];
    const float* Wo   = (const float*)d_in[7];
    const float* bo   = (const float*)d_in[8];
    const float* lnw  = (const float*)d_in[9];
    const float* lnb  = (const float*)d_in[10];
    float* out = (float*)d_out;

    // QKV projections: x @ {Wq,Wk,Wv}^T -> g_q, g_k, g_v
    sgemm_kernel<<<dim3(24, 32), 256>>>(0, x, Wq, Wk, Wv, nullptr, nullptr);
    // gate f
    f_kernel<<<512, 128>>>(x, Wg, bg, mask);
    // RoPE + phi + mask on q and k (in place)
    rope_phi_kernel<<<dim3(8192, 2), 256>>>(mask);
    // gated linear-attention scan -> g_attn (4-way e-split)
    scan_kernel<<<128, 256>>>();
    // output projection + bias + residual -> g_y
    sgemm_kernel<<<dim3(8, 32), 256>>>(1, nullptr, Wo, nullptr, nullptr, bo, x);
    // LayerNorm -> out
    ln_kernel<<<4096, 256>>>(lnw, lnb, out);
}

// round 14
// speedup vs baseline: 1.5381x; 1.5381x over previous
#include <cuda_runtime.h>
#include <cuda_bf16.h>
#include <cstdint>
#include <math.h>

// Problem constants
#define BB 2
#define TT 2048
#define CC 1024
#define HH 16
#define DD 64
#define MROWS (BB*TT)          // 4096
#define KDIM  CC               // 1024
#define NDIM  CC
#define EPS_DEN 1e-6f
#define LN_EPS  1e-5f

// ---------------- scratch (device globals; no allocation allowed) ----------------
__device__ float g_q[MROWS*CC];
__device__ float g_k[MROWS*CC];
__device__ float g_v[MROWS*CC];
__device__ float g_attn[MROWS*CC];
__device__ float g_y[MROWS*CC];
__device__ float g_f[BB*HH*TT];
// bf16 hi/lo decompositions
__device__ __nv_bfloat16 g_xh[MROWS*CC];
__device__ __nv_bfloat16 g_xl[MROWS*CC];
__device__ __nv_bfloat16 g_wh[4*CC*CC];    // Wq | Wk | Wv | Wo
__device__ __nv_bfloat16 g_wl[4*CC*CC];
__device__ __nv_bfloat16 g_ah[MROWS*CC];   // attn hi/lo
__device__ __nv_bfloat16 g_al[MROWS*CC];

// ---------------------------- PTX helpers (baseline features only) ----------------
__device__ __forceinline__ uint32_t smem_u32(const void* p) {
    uint32_t a;
    asm("{ .reg .u64 t; cvta.to.shared.u64 t, %1; cvt.u32.u64 %0, t; }" : "=r"(a) : "l"(p));
    return a;
}
#define CP_ASYNC16(dst, src) \
    asm volatile("cp.async.cg.shared.global [%0], [%1], 16;" :: "r"(dst), "l"(src))
#define CP_COMMIT()  asm volatile("cp.async.commit_group;" ::: "memory")
#define CP_WAIT0()   asm volatile("cp.async.wait_group 0;" ::: "memory")
#define CP_WAIT1()   asm volatile("cp.async.wait_group 1;" ::: "memory")

#define LDSM_X4(r0,r1,r2,r3,addr) \
    asm volatile("ldmatrix.sync.aligned.m8n8.x4.shared.b16 {%0,%1,%2,%3}, [%4];" \
        : "=r"(r0), "=r"(r1), "=r"(r2), "=r"(r3) : "r"(addr))
#define LDSM_X2(r0,r1,addr) \
    asm volatile("ldmatrix.sync.aligned.m8n8.x2.shared.b16 {%0,%1}, [%2];" \
        : "=r"(r0), "=r"(r1) : "r"(addr))

#define MMA16816(d, a, b) \
    asm volatile("mma.sync.aligned.m16n8k16.row.col.f32.bf16.bf16.f32 " \
        "{%0,%1,%2,%3}, {%4,%5,%6,%7}, {%8,%9}, {%0,%1,%2,%3};" \
        : "+f"((d)[0]), "+f"((d)[1]), "+f"((d)[2]), "+f"((d)[3]) \
        : "r"((a)[0]), "r"((a)[1]), "r"((a)[2]), "r"((a)[3]), "r"((b)[0]), "r"((b)[1]))

// ============================================================================
// hi/lo bf16 split: hi = bf16(v), lo = bf16(v - hi). Vectorized by 4.
// ============================================================================
__global__ __launch_bounds__(256) void cvt_kernel(
    const float* __restrict__ in, __nv_bfloat16* __restrict__ hi,
    __nv_bfloat16* __restrict__ lo, int n4)
{
    const int i = blockIdx.x * 256 + threadIdx.x;
    if (i >= n4) return;
    float4 v = ((const float4*)in)[i];
    __nv_bfloat16 h0 = __float2bfloat16(v.x), h1 = __float2bfloat16(v.y);
    __nv_bfloat16 h2 = __float2bfloat16(v.z), h3 = __float2bfloat16(v.w);
    __nv_bfloat16 l0 = __float2bfloat16(v.x - __bfloat162float(h0));
    __nv_bfloat16 l1 = __float2bfloat16(v.y - __bfloat162float(h1));
    __nv_bfloat16 l2 = __float2bfloat16(v.z - __bfloat162float(h2));
    __nv_bfloat16 l3 = __float2bfloat16(v.w - __bfloat162float(h3));
    __nv_bfloat162* hp = (__nv_bfloat162*)(hi + (size_t)i * 4);
    __nv_bfloat162* lp = (__nv_bfloat162*)(lo + (size_t)i * 4);
    hp[0] = __nv_bfloat162(h0, h1); hp[1] = __nv_bfloat162(h2, h3);
    lp[0] = __nv_bfloat162(l0, l1); lp[1] = __nv_bfloat162(l2, l3);
}

// ============================================================================
// HMMA GEMM (mma.sync bf16, hi/lo 3-term): O[m][n] = sum_k A[m][k]*W[n][k].
// 128x128 tile, BK=32, 256 threads (8 warps: 4m x 2n, warp tile 32x64).
// Double-buffered cp.async. All operand tiles K-major, row stride 40 halves.
// mode 0: A = x hi/lo -> g_q/g_k/g_v (grid 24 x 32); mode 1: Wo -> g_y (+bias+res)
// ============================================================================
#define BK 32
#define NCHUNK (KDIM/BK)       // 32
#define ROWB 80                // bytes per smem row (40 halves)
#define ARR_B (128*ROWB)       // 10240 bytes per array
#define STAGE_B (4*ARR_B)      // 40960: Ah | Al | Bh | Bl
#define SMEM_B (2*STAGE_B)     // 81920

__global__ __launch_bounds__(256) void hmma_gemm_kernel(
    int mode,
    const __nv_bfloat16* __restrict__ Ahg, const __nv_bfloat16* __restrict__ Alg,
    const float* __restrict__ bias, const float* __restrict__ residual)
{
    extern __shared__ char smem[];
    const uint32_t sb = smem_u32(smem);
    const int tid  = threadIdx.x;
    const int warp = tid >> 5;
    const int lane = tid & 31;
    const int mw   = warp >> 1;          // 0..3
    const int nw   = warp & 1;           // 0..1

    const int wsel = (mode == 0) ? (blockIdx.x >> 3) : 3;
    const int n0   = (mode == 0) ? (blockIdx.x & 7) * 128 : blockIdx.x * 128;
    const int m0   = blockIdx.y * 128;
    float* O = (mode == 0) ? ((wsel == 0) ? g_q : (wsel == 1 ? g_k : g_v)) : g_y;

    const __nv_bfloat16* Ath = Ahg + (size_t)m0 * KDIM;
    const __nv_bfloat16* Atl = Alg + (size_t)m0 * KDIM;
    const __nv_bfloat16* Wth = g_wh + (size_t)(wsel * CC + n0) * KDIM;
    const __nv_bfloat16* Wtl = g_wl + (size_t)(wsel * CC + n0) * KDIM;
    const __nv_bfloat16* bases[4] = { Ath, Atl, Wth, Wtl };

    // per-thread cp.async geometry: 2048 16B-chunks per stage, 8 per thread
    const __nv_bfloat16* srcs[8];
    uint32_t dsts[8];
    #pragma unroll
    for (int i = 0; i < 8; i++) {
        const int c   = i * 256 + tid;
        const int arr = c >> 9;
        const int rem = c & 511;
        const int row = rem >> 2;
        const int u   = rem & 3;
        srcs[i] = bases[arr] + (size_t)row * KDIM + u * 8;   // + k0 later
        dsts[i] = sb + arr * ARR_B + row * ROWB + u * 16;    // + stage later
    }

    float d[2][8][4];
    #pragma unroll
    for (int i = 0; i < 2; i++)
        #pragma unroll
        for (int j = 0; j < 8; j++)
            #pragma unroll
            for (int q = 0; q < 4; q++) d[i][j][q] = 0.f;

    // ldmatrix lane addressing (offsets within a stage)
    const uint32_t a_row = (uint32_t)(mw * 32 + (lane & 15));
    const uint32_t a_koff = (uint32_t)((lane >> 4) * 8);
    const uint32_t b_row = (uint32_t)(nw * 64 + (lane & 7));
    const uint32_t b_koff = (uint32_t)(((lane >> 3) & 1) * 8);

    // prologue: stage 0 loads
    #pragma unroll
    for (int i = 0; i < 8; i++) CP_ASYNC16(dsts[i], srcs[i]);
    CP_COMMIT();

    for (int c = 0; c < NCHUNK; c++) {
        if (c + 1 < NCHUNK) {
            const uint32_t st = ((c + 1) & 1) * STAGE_B;
            const int k0 = (c + 1) * BK;
            #pragma unroll
            for (int i = 0; i < 8; i++) CP_ASYNC16(dsts[i] + st, srcs[i] + k0);
            CP_COMMIT();
            CP_WAIT1();
        } else {
            CP_WAIT0();
        }
        __syncthreads();

        const uint32_t stage = sb + (c & 1) * STAGE_B;
        #pragma unroll
        for (int ks = 0; ks < 2; ks++) {
            const uint32_t kh = (uint32_t)(ks * 16);
            uint32_t ah[2][4], al[2][4];
            #pragma unroll
            for (int i = 0; i < 2; i++) {
                const uint32_t ra = stage + (a_row + i * 16) * ROWB + (kh + a_koff) * 2;
                LDSM_X4(ah[i][0], ah[i][1], ah[i][2], ah[i][3], ra);
                LDSM_X4(al[i][0], al[i][1], al[i][2], al[i][3], ra + ARR_B);
            }
            uint32_t bh[8][2], bl[8][2];
            #pragma unroll
            for (int j = 0; j < 8; j++) {
                const uint32_t rb = stage + 2 * ARR_B + (b_row + j * 8) * ROWB + (kh + b_koff) * 2;
                LDSM_X2(bh[j][0], bh[j][1], rb);
                LDSM_X2(bl[j][0], bl[j][1], rb + ARR_B);
            }
            #pragma unroll
            for (int i = 0; i < 2; i++)
                #pragma unroll
                for (int j = 0; j < 8; j++) {
                    MMA16816(d[i][j], ah[i], bh[j]);
                    MMA16816(d[i][j], ah[i], bl[j]);
                    MMA16816(d[i][j], al[i], bh[j]);
                }
        }
        __syncthreads();
    }

    // epilogue: D fragment -> global (+bias +residual)
    #pragma unroll
    for (int i = 0; i < 2; i++) {
        const int r0 = m0 + mw * 32 + i * 16 + (lane >> 2);
        const int r1 = r0 + 8;
        #pragma unroll
        for (int j = 0; j < 8; j++) {
            const int gn = n0 + nw * 64 + j * 8 + (lane & 3) * 2;
            float2 v0 = make_float2(d[i][j][0], d[i][j][1]);
            float2 v1 = make_float2(d[i][j][2], d[i][j][3]);
            if (bias) {
                float2 bb = *(const float2*)(bias + gn);
                v0.x += bb.x; v0.y += bb.y; v1.x += bb.x; v1.y += bb.y;
            }
            if (residual) {
                float2 q0 = *(const float2*)(residual + (size_t)r0 * NDIM + gn);
                float2 q1 = *(const float2*)(residual + (size_t)r1 * NDIM + gn);
                v0.x += q0.x; v0.y += q0.y; v1.x += q1.x; v1.y += q1.y;
            }
            *(float2*)(O + (size_t)r0 * NDIM + gn) = v0;
            *(float2*)(O + (size_t)r1 * NDIM + gn) = v1;
        }
    }
}

// ============================================================================
// gate: f[b][h][t] = mask-adjusted clip(sigmoid(x_row . Wg[h] + bg[h]))
// ============================================================================
__global__ __launch_bounds__(128) void f_kernel(
    const float* __restrict__ x, const float* __restrict__ Wg,
    const float* __restrict__ bg, const int* __restrict__ mask)
{
    const int tid = threadIdx.x;
    const int r = tid >> 4, h = tid & 15;
    const int row = blockIdx.x * 8 + r;
    const float4* xr = (const float4*)(x + (size_t)row * CC);
    const float4* wr = (const float4*)(Wg + (size_t)h * CC);
    float s = 0.f;
    #pragma unroll 8
    for (int kk = 0; kk < CC/4; kk++) {
        float4 a = xr[kk], w = wr[kk];
        s = fmaf(a.x, w.x, s); s = fmaf(a.y, w.y, s);
        s = fmaf(a.z, w.z, s); s = fmaf(a.w, w.w, s);
    }
    s += bg[h];
    float fv = 1.0f / (1.0f + expf(-s));
    fv = fminf(fmaxf(fv, 0.01f), 0.999f);
    const float mk = (float)mask[row];
    fv = fv * mk + (1.0f - mk);
    const int b = row >> 11, t = row & (TT - 1);
    g_f[((size_t)(b * HH + h)) * TT + t] = fv;
}

// ============================================================================
// RoPE + phi (elu+1) + mask, in place on g_q / g_k. One warp per (b,t,h).
// ============================================================================
__global__ __launch_bounds__(256) void rope_phi_kernel(const int* __restrict__ mask)
{
    const int wid  = blockIdx.x * 8 + (threadIdx.x >> 5);
    const int lane = threadIdx.x & 31;
    const int h    = wid & 15;
    const int row  = wid >> 4;
    const int t    = row & (TT - 1);

    float* ptr = (blockIdx.y ? g_k : g_q) + (size_t)row * CC + h * DD;
    const float x1 = ptr[lane];
    const float x2 = ptr[lane + 32];

    const float inv = (float)(1.0 / pow(10000.0, (double)lane * (1.0 / 32.0)));
    const float fr  = (float)t * inv;
    float c, s;
    sincosf(fr, &s, &c);

    float y1 = x1 * c - x2 * s;
    float y2 = x2 * c + x1 * s;
    y1 = (y1 > 0.f) ? (y1 + 1.f) : expf(y1);
    y2 = (y2 > 0.f) ? (y2 + 1.f) : expf(y2);
    const float mk = (float)mask[row];
    ptr[lane]      = y1 * mk;
    ptr[lane + 32] = y2 * mk;
}

// ============================================================================
// Gated linear-attention scan, 4-way e-split, reductions batched over 4 steps.
// The S/m updates (lat-4 FMA chain) are the only carried dependence; num/den
// shfl trees are outputs, so 4 steps' reductions run as 8 interleaved chains.
// ============================================================================
#define SCHUNK 16
__global__ __launch_bounds__(256) void scan_kernel()
{
    const int bx = blockIdx.x;
    const int bh = bx >> 2;
    const int e0 = (bx & 3) * 16;
    const int b = bh >> 4, h = bh & 15;
    const int tid = threadIdx.x;
    const int g = tid & 15;
    const int e = e0 + (tid >> 4);

    __shared__ float qs[SCHUNK][64], ks[SCHUNK][64], vs[SCHUNK][64], fs[SCHUNK];

    float S[4], m[4];
    #pragma unroll
    for (int j = 0; j < 4; j++) { S[j] = 0.f; m[j] = 0.f; }

    const size_t base = (size_t)(b * TT) * CC + h * DD;
    const float* fptr = g_f + (size_t)bh * TT;

    const int r  = tid >> 4;
    const int cv = (tid & 15) * 4;

    for (int c = 0; c < TT / SCHUNK; c++) {
        __syncthreads();
        {
            const size_t roff = base + (size_t)(c * SCHUNK + r) * CC + cv;
            *(float4*)&qs[r][cv] = *(const float4*)(g_q + roff);
            *(float4*)&ks[r][cv] = *(const float4*)(g_k + roff);
            *(float4*)&vs[r][cv] = *(const float4*)(g_v + roff);
            if (tid < SCHUNK) fs[tid] = fptr[c * SCHUNK + tid];
        }
        __syncthreads();

        #pragma unroll
        for (int ib = 0; ib < SCHUNK; ib += 4) {
            float num[4], den[4];
            // phase 1: state updates + per-thread partials for 4 steps
            #pragma unroll
            for (int u = 0; u < 4; u++) {
                const int i = ib + u;
                const float ft = fs[i];
                const float ve = vs[i][e];
                float kreg[4], qreg[4];
                *(float4*)&kreg[0] = *(const float4*)&ks[i][g*4];
                *(float4*)&qreg[0] = *(const float4*)&qs[i][g*4];
                float nu = 0.f, de = 0.f;
                #pragma unroll
                for (int j = 0; j < 4; j++) {
                    const float kv = kreg[j] * ve;
                    S[j] = fmaf(ft, S[j], kv);
                    nu   = fmaf(qreg[j], S[j], nu);
                    m[j] = fmaf(ft, m[j], kreg[j]);
                    de   = fmaf(qreg[j], m[j], de);
                }
                num[u] = nu; den[u] = de;
            }
            // phase 2: 8 interleaved shfl-reduction chains (4 levels)
            #pragma unroll
            for (int o = 1; o <= 8; o <<= 1) {
                #pragma unroll
                for (int u = 0; u < 4; u++) {
                    num[u] += __shfl_xor_sync(0xFFFFFFFFu, num[u], o);
                    den[u] += __shfl_xor_sync(0xFFFFFFFFu, den[u], o);
                }
            }
            // phase 3: stores
            if (g == 0) {
                #pragma unroll
                for (int u = 0; u < 4; u++) {
                    g_attn[base + (size_t)(c * SCHUNK + ib + u) * CC + e] =
                        num[u] / fmaxf(den[u], EPS_DEN);
                }
            }
        }
    }
}

// ============================================================================
// LayerNorm over rows of g_y -> out.
// ============================================================================
__global__ __launch_bounds__(256) void ln_kernel(
    const float* __restrict__ lnw, const float* __restrict__ lnb,
    float* __restrict__ out)
{
    const int row = blockIdx.x;
    const int tid = threadIdx.x;
    const float4 v = ((const float4*)(g_y + (size_t)row * CC))[tid];
    float s  = v.x + v.y + v.z + v.w;
    float ss = v.x*v.x + v.y*v.y + v.z*v.z + v.w*v.w;

    #pragma unroll
    for (int o = 16; o > 0; o >>= 1) {
        s  += __shfl_xor_sync(0xFFFFFFFFu, s,  o);
        ss += __shfl_xor_sync(0xFFFFFFFFu, ss, o);
    }
    __shared__ float red[16];
    const int wid = tid >> 5, lane = tid & 31;
    if (lane == 0) { red[wid] = s; red[wid + 8] = ss; }
    __syncthreads();
    float ts = 0.f, tss = 0.f;
    #pragma unroll
    for (int i = 0; i < 8; i++) { ts += red[i]; tss += red[i + 8]; }

    const float mu   = ts * (1.0f / CC);
    const float var  = tss * (1.0f / CC) - mu * mu;
    const float rstd = rsqrtf(var + LN_EPS);

    const float4 wv = ((const float4*)lnw)[tid];
    const float4 bv = ((const float4*)lnb)[tid];
    float4 o;
    o.x = (v.x - mu) * rstd * wv.x + bv.x;
    o.y = (v.y - mu) * rstd * wv.y + bv.y;
    o.z = (v.z - mu) * rstd * wv.z + bv.z;
    o.w = (v.w - mu) * rstd * wv.w + bv.w;
    ((float4*)(out + (size_t)row * CC))[tid] = o;
}

// ============================================================================
extern "C" void kernel_launch(void* const* d_in, const int* in_sizes, int n_in,
                              void* d_out, int out_size)
{
    const float* x    = (const float*)d_in[0];
    const int*   mask = (const int*)  d_in[1];
    const float* Wq   = (const float*)d_in[2];
    const float* Wk   = (const float*)d_in[3];
    const float* Wv   = (const float*)d_in[4];
    const float* Wg   = (const float*)d_in[5];
    const float* bg   = (const float*)d_in[6];
    const float* Wo   = (const float*)d_in[7];
    const float* bo   = (const float*)d_in[8];
    const float* lnw  = (const float*)d_in[9];
    const float* lnb  = (const float*)d_in[10];
    float* out = (float*)d_out;

    cudaFuncSetAttribute(hmma_gemm_kernel, cudaFuncAttributeMaxDynamicSharedMemorySize, SMEM_B);

    __nv_bfloat16 *xh, *xl, *wh, *wl, *ah, *al;
    float* attn_ptr;
    cudaGetSymbolAddress((void**)&xh, g_xh);
    cudaGetSymbolAddress((void**)&xl, g_xl);
    cudaGetSymbolAddress((void**)&wh, g_wh);
    cudaGetSymbolAddress((void**)&wl, g_wl);
    cudaGetSymbolAddress((void**)&ah, g_ah);
    cudaGetSymbolAddress((void**)&al, g_al);
    cudaGetSymbolAddress((void**)&attn_ptr, g_attn);

    // hi/lo conversions
    cvt_kernel<<<4096, 256>>>(x,  xh, xl, MROWS*CC/4);
    cvt_kernel<<<1024, 256>>>(Wq, wh + 0*CC*CC, wl + 0*CC*CC, CC*CC/4);
    cvt_kernel<<<1024, 256>>>(Wk, wh + 1*CC*CC, wl + 1*CC*CC, CC*CC/4);
    cvt_kernel<<<1024, 256>>>(Wv, wh + 2*CC*CC, wl + 2*CC*CC, CC*CC/4);
    cvt_kernel<<<1024, 256>>>(Wo, wh + 3*CC*CC, wl + 3*CC*CC, CC*CC/4);

    // QKV projections on tensor cores (HMMA) -> g_q, g_k, g_v
    hmma_gemm_kernel<<<dim3(24, 32), 256, SMEM_B>>>(0, xh, xl, nullptr, nullptr);
    // gate f
    f_kernel<<<512, 128>>>(x, Wg, bg, mask);
    // RoPE + phi + mask on q and k (in place)
    rope_phi_kernel<<<dim3(8192, 2), 256>>>(mask);
    // gated linear-attention scan -> g_attn
    scan_kernel<<<128, 256>>>();
    // attn hi/lo + output projection (+ bias + residual) -> g_y
    cvt_kernel<<<4096, 256>>>(attn_ptr, ah, al, MROWS*CC/4);
    hmma_gemm_kernel<<<dim3(8, 32), 256, SMEM_B>>>(1, ah, al, bo, x);
    // LayerNorm -> out
    ln_kernel<<<4096, 256>>>(lnw, lnb, out);
}